// round 11
// baseline (speedup 1.0000x reference)
#include <cuda_runtime.h>
#include <math.h>
#include <stdint.h>

// Problem constants
#define HID    2048
#define BATCH  2
#define SEQ    2048
#define NHEADS 16
#define HD     128
#define MROWS  (BATCH * SEQ)   // 4096

// ---------------------------------------------------------------------------
// Scratch (static __device__ arrays — no allocation anywhere)
// ---------------------------------------------------------------------------
__device__ float g_Xp [(size_t)MROWS * HID];          // X, tf32, permuted A layout
__device__ float g_Wp [(size_t)4 * HID * HID];        // W*, tf32, TRANSPOSED [n][k] permuted
__device__ float g_Q  [(size_t)MROWS * HID];          // Q tf32, permuted per-head
__device__ float g_K  [(size_t)MROWS * HID];          // K tf32, permuted per-head
__device__ float g_V  [(size_t)MROWS * HID];          // V tf32, plain
__device__ float g_CTXp[(size_t)MROWS * HID];         // ctx tf32, permuted A layout

// ---------------------------------------------------------------------------
// Helpers
// ---------------------------------------------------------------------------
__device__ __forceinline__ float f2tf32f(float f) {
    uint32_t r;
    asm("cvt.rna.tf32.f32 %0, %1;" : "=r"(r) : "f"(f));
    return __uint_as_float(r);
}
__device__ __forceinline__ uint32_t smem_u32(const void* p) {
    uint32_t a;
    asm("{ .reg .u64 t; cvta.to.shared.u64 t, %1; cvt.u32.u64 %0, t; }"
        : "=r"(a) : "l"(p));
    return a;
}
__device__ __forceinline__ void cp16(uint32_t dst, const void* src) {
    asm volatile("cp.async.cg.shared.global [%0], [%1], 16;"
                 :: "r"(dst), "l"(src));
}
__device__ __forceinline__ void cp_commit() {
    asm volatile("cp.async.commit_group;");
}
template <int N>
__device__ __forceinline__ void cp_wait() {
    asm volatile("cp.async.wait_group %0;" :: "n"(N));
}

__device__ __forceinline__ void mma_tf32(float& d0, float& d1, float& d2, float& d3,
                                         float a0, float a1, float a2, float a3,
                                         float b0, float b1)
{
    asm volatile(
        "mma.sync.aligned.m16n8k8.row.col.f32.tf32.tf32.f32 "
        "{%0,%1,%2,%3}, {%4,%5,%6,%7}, {%8,%9}, {%0,%1,%2,%3};"
        : "+f"(d0), "+f"(d1), "+f"(d2), "+f"(d3)
        : "r"(__float_as_uint(a0)), "r"(__float_as_uint(a1)),
          "r"(__float_as_uint(a2)), "r"(__float_as_uint(a3)),
          "r"(__float_as_uint(b0)), "r"(__float_as_uint(b1)));
}

// ---------------------------------------------------------------------------
// Prep:
//   z=0   : X -> g_Xp  (tf32, permuted A layout)
//   z=1..4: W* -> g_Wp (tf32, TRANSPOSED to [n][k], permuted A layout)
// Permuted layout per 32-float k-block of row r:
//   element k -> p=(k%4)*8+k/4, stored at ((p>>2)^(r&7))*4 + (p&3)
// ---------------------------------------------------------------------------
__global__ __launch_bounds__(256)
void prep_kernel(const float* __restrict__ X,
                 const float* __restrict__ Wq, const float* __restrict__ Wk,
                 const float* __restrict__ Wv, const float* __restrict__ Wo)
{
    const int tid = threadIdx.x;
    const int z = blockIdx.z;
    if (z == 0) {
        const int idx = blockIdx.x * 256 + tid;   // float4 index
        int r   = idx >> 9;
        int rem = idx & 511;
        int c   = rem >> 3;
        int j   = rem & 7;
        float4 v = *(const float4*)(X + (size_t)r * HID + c * 32 + j * 4);
        float* dst = g_Xp + (size_t)r * HID + c * 32;
        const float vv[4] = { v.x, v.y, v.z, v.w };
#pragma unroll
        for (int e = 0; e < 4; e++) {
            int p = e * 8 + j;
            dst[(((p >> 2) ^ (r & 7)) << 2) + (p & 3)] = f2tf32f(vv[e]);
        }
    } else {
        // 64x64 tiled transpose: W[k][n] -> Wt[n][k] (permuted, tf32)
        if (blockIdx.x >= 1024) return;
        __shared__ float ts[64][65];
        const float* W = (z == 1) ? Wq : (z == 2) ? Wk : (z == 3) ? Wv : Wo;
        float* Wt = g_Wp + (size_t)(z - 1) * HID * HID;
        const int k0 = (blockIdx.x & 31) * 64;
        const int n0 = (blockIdx.x >> 5) * 64;

#pragma unroll
        for (int it = 0; it < 4; it++) {
            int idx = tid + it * 256;
            int kk  = idx >> 4;             // 0..63
            int jj  = idx & 15;             // float4 along n
            float4 v = *(const float4*)(W + (size_t)(k0 + kk) * HID + n0 + jj * 4);
            ts[jj * 4 + 0][kk] = v.x;
            ts[jj * 4 + 1][kk] = v.y;
            ts[jj * 4 + 2][kk] = v.z;
            ts[jj * 4 + 3][kk] = v.w;
        }
        __syncthreads();

#pragma unroll
        for (int it = 0; it < 4; it++) {
            int idx = tid + it * 256;
            int n   = idx >> 4;             // 0..63 (output row)
            int rest = idx & 15;
            int c   = rest >> 3;            // 32-k block (0..1)
            int j   = rest & 7;
            float* dst = Wt + (size_t)(n0 + n) * HID + k0 + c * 32;
            int xr = (n0 + n) & 7;
#pragma unroll
            for (int e = 0; e < 4; e++) {
                float v = ts[n][c * 32 + j * 4 + e];
                int p = e * 8 + j;
                dst[(((p >> 2) ^ xr) << 2) + (p & 3)] = f2tf32f(v);
            }
        }
    }
}

// ---------------------------------------------------------------------------
// tf32 mma.sync GEMM v4: C = Aperm @ WtPerm + bias
// Both operands in the permuted layout -> all fragment loads are LDS.128.
// CTA 128x128, BK=32, 8 warps (2Mx4N), 3-stage cp.async pipeline, 2 CTAs/SM.
// mode 0: store tf32, permuted per-head layout (Q, K)
// mode 1: store tf32, plain (V)
// mode 2: store fp32, plain (final out)
// ---------------------------------------------------------------------------
#define NSTAGE   3
#define ASTG     4096                     // floats per operand stage (128x32)
#define GEMM_SMEM_FLOATS (NSTAGE * 2 * ASTG)
#define GEMM_SMEM_BYTES  (GEMM_SMEM_FLOATS * 4)

__device__ __forceinline__ void tf32_gemm_body(const float* __restrict__ Ap,
                                               const float* __restrict__ Wt,
                                               const float* __restrict__ bias,
                                               float* __restrict__ C,
                                               int mode)
{
    extern __shared__ float sm[];
    float* smA = sm;
    float* smB = sm + NSTAGE * ASTG;
    const uint32_t smA_u = smem_u32(smA);
    const uint32_t smB_u = smem_u32(smB);

    const int tid   = threadIdx.x;
    const int lane  = tid & 31;
    const int wid   = tid >> 5;
    const int warpM = wid >> 2;
    const int warpN = wid & 3;
    const int csel  = lane & 3;
    const int g     = lane >> 2;

    const int m0 = blockIdx.y * 128;
    const int n0 = blockIdx.x * 128;

    const int lr = tid >> 3;              // row 0..31 (+32 per iter)
    const int lj = tid & 7;               // float4 within 32-float block

    const float* Abase = Ap + (size_t)(m0 + lr) * HID + lj * 4;
    const float* Bbase = Wt + (size_t)(n0 + lr) * HID + lj * 4;
    const uint32_t dA = smA_u + (lr * 32 + lj * 4) * 4;
    const uint32_t dB = smB_u + (lr * 32 + lj * 4) * 4;

    auto load_chunk = [&](int c, int st) {
        const float* As = Abase + c * 32;
        const float* Bs = Bbase + c * 32;
        const uint32_t dAs = dA + st * (ASTG * 4);
        const uint32_t dBs = dB + st * (ASTG * 4);
#pragma unroll
        for (int i = 0; i < 4; i++) {
            cp16(dAs + i * 32 * 32 * 4, As + (size_t)i * 32 * HID);
            cp16(dBs + i * 32 * 32 * 4, Bs + (size_t)i * 32 * HID);
        }
        cp_commit();
    };

    float acc[4][4][4];
#pragma unroll
    for (int mt = 0; mt < 4; mt++)
#pragma unroll
        for (int nt = 0; nt < 4; nt++)
#pragma unroll
            for (int e = 0; e < 4; e++) acc[mt][nt][e] = 0.f;

    auto compute = [&](int st) {
        const float* a = smA + st * ASTG;
        const float* b = smB + st * ASTG;
#pragma unroll
        for (int half = 0; half < 2; half++) {
            const int q = 2 * csel + half;
            float4 A0[4], A8[4];
#pragma unroll
            for (int mt = 0; mt < 4; mt++) {
                int r0 = warpM * 64 + mt * 16 + g;
                int r8 = r0 + 8;
                A0[mt] = *(const float4*)(a + r0 * 32 + ((q ^ (r0 & 7)) * 4));
                A8[mt] = *(const float4*)(a + r8 * 32 + ((q ^ (r8 & 7)) * 4));
            }
#pragma unroll
            for (int nt = 0; nt < 4; nt++) {
                int n = warpN * 32 + nt * 8 + g;
                float4 Bf = *(const float4*)(b + n * 32 + ((q ^ (n & 7)) * 4));
#pragma unroll
                for (int mt = 0; mt < 4; mt++) {
                    mma_tf32(acc[mt][nt][0], acc[mt][nt][1],
                             acc[mt][nt][2], acc[mt][nt][3],
                             A0[mt].x, A8[mt].x, A0[mt].y, A8[mt].y, Bf.x, Bf.y);
                    mma_tf32(acc[mt][nt][0], acc[mt][nt][1],
                             acc[mt][nt][2], acc[mt][nt][3],
                             A0[mt].z, A8[mt].z, A0[mt].w, A8[mt].w, Bf.z, Bf.w);
                }
            }
        }
    };

    load_chunk(0, 0);
    load_chunk(1, 1);

    const int NC = HID / 32;
    for (int c = 0; c < NC; c++) {
        if (c == NC - 1) cp_wait<0>(); else cp_wait<1>();
        __syncthreads();
        compute(c % NSTAGE);
        if (c + 2 < NC) load_chunk(c + 2, (c + 2) % NSTAGE);
    }

    if (mode == 0) {
        const int xg = g & 7;
#pragma unroll
        for (int mt = 0; mt < 4; mt++) {
            int rg0 = m0 + warpM * 64 + mt * 16 + g;
            int rg1 = rg0 + 8;
#pragma unroll
            for (int nt = 0; nt < 4; nt++) {
                int kin0 = nt * 8 + 2 * csel;
                int colb = n0 + warpN * 32;
                int p0   = (kin0 & 3) * 8 + (kin0 >> 2);
                int x    = p0 >> 2, lo = p0 & 3;
                int idx0 = ((x ^ xg) << 2) + lo;
                int idx1 = (((x + 2) ^ xg) << 2) + lo;
                float b0 = __ldg(bias + colb + kin0);
                float b1 = __ldg(bias + colb + kin0 + 1);
                C[(size_t)rg0 * HID + colb + idx0] = f2tf32f(acc[mt][nt][0] + b0);
                C[(size_t)rg0 * HID + colb + idx1] = f2tf32f(acc[mt][nt][1] + b1);
                C[(size_t)rg1 * HID + colb + idx0] = f2tf32f(acc[mt][nt][2] + b0);
                C[(size_t)rg1 * HID + colb + idx1] = f2tf32f(acc[mt][nt][3] + b1);
            }
        }
    } else {
#pragma unroll
        for (int mt = 0; mt < 4; mt++) {
            int row = m0 + warpM * 64 + mt * 16 + g;
#pragma unroll
            for (int nt = 0; nt < 4; nt++) {
                int col = n0 + warpN * 32 + nt * 8 + 2 * csel;
                float b0 = __ldg(bias + col);
                float b1 = __ldg(bias + col + 1);
                float v0 = acc[mt][nt][0] + b0, v1 = acc[mt][nt][1] + b1;
                float v2 = acc[mt][nt][2] + b0, v3 = acc[mt][nt][3] + b1;
                if (mode == 1) {
                    v0 = f2tf32f(v0); v1 = f2tf32f(v1);
                    v2 = f2tf32f(v2); v3 = f2tf32f(v3);
                }
                *(float2*)(C + (size_t)row * HID + col)       = make_float2(v0, v1);
                *(float2*)(C + (size_t)(row + 8) * HID + col) = make_float2(v2, v3);
            }
        }
    }
}

__global__ __launch_bounds__(256, 2)
void qkv_gemm_tc(const float* __restrict__ bq,
                 const float* __restrict__ bk,
                 const float* __restrict__ bv)
{
    const float* Wz; const float* b; float* Cp; int mode;
    if (blockIdx.z == 0)      { Wz = g_Wp;                     b = bq; Cp = g_Q; mode = 0; }
    else if (blockIdx.z == 1) { Wz = g_Wp + (size_t)HID*HID;   b = bk; Cp = g_K; mode = 0; }
    else                      { Wz = g_Wp + (size_t)2*HID*HID; b = bv; Cp = g_V; mode = 1; }
    tf32_gemm_body(g_Xp, Wz, b, Cp, mode);
}

__global__ __launch_bounds__(256, 2)
void out_gemm_tc(const float* __restrict__ bo, float* __restrict__ out)
{
    tf32_gemm_body(g_CTXp, g_Wp + (size_t)3 * HID * HID, bo, out, 2);
}

// ---------------------------------------------------------------------------
// Attention v6: 512 threads (16 warps). BM=128.
// S phase: warp tile 16x32 (8 warpM x 2 warpN). PV: warp tile 16x64.
// K reloaded during softmax+PV (dead after S), V double-buffered.
// Output -> g_CTXp (permuted A layout, tf32).
// ---------------------------------------------------------------------------
#define SSTRIDE 68
#define VSTRIDE 136
#define VBUF    (64 * VSTRIDE)
#define ATTN_SMEM_FLOATS (16384 + 8192 + 2 * VBUF + 128 * SSTRIDE + 384)
#define ATTN_SMEM_BYTES  (ATTN_SMEM_FLOATS * 4)

__global__ __launch_bounds__(512)
void attn_kernel()
{
    extern __shared__ float smf[];
    float* Qs  = smf;                    // 4 chunks x 128 x 32 (permuted tf32)
    float* Ks  = Qs + 16384;             // 4 chunks x 64 x 32
    float* Vs  = Ks + 8192;              // 2 x (64 x VSTRIDE)
    float* Ss  = Vs + 2 * VBUF;          // 128 x SSTRIDE
    float* m_s = Ss + 128 * SSTRIDE;     // 128
    float* l_s = m_s + 128;
    float* a_s = l_s + 128;
    const uint32_t Qs_u = smem_u32(Qs);
    const uint32_t Ks_u = smem_u32(Ks);
    const uint32_t Vs_u = smem_u32(Vs);

    const int tid  = threadIdx.x;
    const int lane = tid & 31;
    const int wid  = tid >> 5;           // 0..15
    const int warpM = wid >> 1;          // 0..7 (16-row slabs)
    const int warpN = wid & 1;           // 0..1
    const int csel = lane & 3;
    const int g    = lane >> 2;

    const int bh  = blockIdx.y;
    const int b   = bh >> 4;
    const int h   = bh & 15;
    const int q0  = blockIdx.x * 128;
    const size_t rowbase = (size_t)b * SEQ;
    const float scale = 0.08838834764831845f;   // 1/sqrt(128)

    const int pm0 = warpM * 16;
    const int pn0 = warpN * 64;          // PV col slab

    // ---- Q tile: 128 x 128 -> permuted (8 iters x 512 threads) ----
    {
        const float* Qg = g_Q + (rowbase + q0) * HID + h * HD;
#pragma unroll
        for (int it = 0; it < 8; it++) {
            int idx = tid + it * 512;
            int r   = idx >> 5;
            int rem = idx & 31;
            cp16(Qs_u + (((rem >> 3) * 4096 + r * 32 + (rem & 7) * 4) * 4),
                 Qg + (size_t)r * HID + rem * 4);
        }
    }
    // ---- preload K/V tile 0 ----
    {
        const float* Kg = g_K + rowbase * HID + h * HD;
        const float* Vg = g_V + rowbase * HID + h * HD;
#pragma unroll
        for (int it = 0; it < 4; it++) {
            int idx = tid + it * 512;
            int r   = idx >> 5;
            int rem = idx & 31;
            cp16(Ks_u + (((rem >> 3) * 2048 + r * 32 + (rem & 7) * 4) * 4),
                 Kg + (size_t)r * HID + rem * 4);
            cp16(Vs_u + ((r * VSTRIDE + rem * 4) * 4),
                 Vg + (size_t)r * HID + rem * 4);
        }
        cp_commit();
    }
    if (tid < 128) { m_s[tid] = -INFINITY; l_s[tid] = 0.f; }

    float accO[8][4];
#pragma unroll
    for (int nt = 0; nt < 8; nt++)
#pragma unroll
        for (int e = 0; e < 4; e++) accO[nt][e] = 0.f;

    const int NT = SEQ / 64;   // 32
    for (int jt = 0; jt < NT; jt++) {
        cp_wait<0>();
        __syncthreads();

        // ---- S = (Q K^T): warp tile 16 x 32 ----
        {
            float accS[4][4];
#pragma unroll
            for (int nt = 0; nt < 4; nt++)
#pragma unroll
                for (int e = 0; e < 4; e++) accS[nt][e] = 0.f;

#pragma unroll
            for (int ch = 0; ch < 4; ch++) {
                const float* qa = Qs + ch * 4096;
                const float* kb = Ks + ch * 2048;
#pragma unroll
                for (int half = 0; half < 2; half++) {
                    const int q = 2 * csel + half;
                    int r0 = pm0 + g;
                    int r8 = r0 + 8;
                    float4 A0 = *(const float4*)(qa + r0 * 32 + ((q ^ (r0 & 7)) * 4));
                    float4 A8 = *(const float4*)(qa + r8 * 32 + ((q ^ (r8 & 7)) * 4));
#pragma unroll
                    for (int nt = 0; nt < 4; nt++) {
                        int n = warpN * 32 + nt * 8 + g;
                        float4 Bf = *(const float4*)(kb + n * 32 + ((q ^ (n & 7)) * 4));
                        mma_tf32(accS[nt][0], accS[nt][1], accS[nt][2], accS[nt][3],
                                 A0.x, A8.x, A0.y, A8.y, Bf.x, Bf.y);
                        mma_tf32(accS[nt][0], accS[nt][1], accS[nt][2], accS[nt][3],
                                 A0.z, A8.z, A0.w, A8.w, Bf.z, Bf.w);
                    }
                }
            }
            int row0 = pm0 + g;
#pragma unroll
            for (int nt = 0; nt < 4; nt++) {
                int col = warpN * 32 + nt * 8 + 2 * csel;
                *(float2*)(Ss + row0 * SSTRIDE + col) =
                    make_float2(accS[nt][0] * scale, accS[nt][1] * scale);
                *(float2*)(Ss + (row0 + 8) * SSTRIDE + col) =
                    make_float2(accS[nt][2] * scale, accS[nt][3] * scale);
            }
        }
        __syncthreads();       // Ks consumed; Ss written

        // ---- prefetch K/V for jt+1 (overlaps softmax + PV) ----
        if (jt + 1 < NT) {
            const float* Kg = g_K + (rowbase + (jt + 1) * 64) * HID + h * HD;
            const float* Vg = g_V + (rowbase + (jt + 1) * 64) * HID + h * HD;
            const uint32_t vb = ((jt + 1) & 1) * (VBUF * 4);
#pragma unroll
            for (int it = 0; it < 4; it++) {
                int idx = tid + it * 512;
                int r   = idx >> 5;
                int rem = idx & 31;
                cp16(Ks_u + (((rem >> 3) * 2048 + r * 32 + (rem & 7) * 4) * 4),
                     Kg + (size_t)r * HID + rem * 4);
                cp16(Vs_u + vb + ((r * VSTRIDE + rem * 4) * 4),
                     Vg + (size_t)r * HID + rem * 4);
            }
            cp_commit();
        }

        // ---- online softmax: 4 threads per row (16 cols each) ----
        {
            const int r  = tid >> 2;
            const int qd = tid & 3;
            float* srow = Ss + r * SSTRIDE + qd * 16;
            float mold = m_s[r];
            float mx = mold;
#pragma unroll
            for (int c = 0; c < 16; c++) mx = fmaxf(mx, srow[c]);
            mx = fmaxf(mx, __shfl_xor_sync(0xFFFFFFFFu, mx, 1));
            mx = fmaxf(mx, __shfl_xor_sync(0xFFFFFFFFu, mx, 2));
            float ls = 0.f;
#pragma unroll
            for (int c = 0; c < 16; c++) {
                float p = __expf(srow[c] - mx);
                srow[c] = f2tf32f(p);
                ls += p;
            }
            ls += __shfl_xor_sync(0xFFFFFFFFu, ls, 1);
            ls += __shfl_xor_sync(0xFFFFFFFFu, ls, 2);
            if (qd == 0) {
                float alpha = __expf(mold - mx);
                m_s[r] = mx;
                l_s[r] = l_s[r] * alpha + ls;
                a_s[r] = alpha;
            }
        }
        __syncthreads();

        // ---- O += P @ V : warp tile 16 x 64 ----
        {
            const float* Vb = Vs + (jt & 1) * VBUF;
            float al0 = a_s[pm0 + g];
            float al1 = a_s[pm0 + g + 8];
#pragma unroll
            for (int nt = 0; nt < 8; nt++) {
                accO[nt][0] *= al0;  accO[nt][1] *= al0;
                accO[nt][2] *= al1;  accO[nt][3] *= al1;
            }
            const float* Pr0 = Ss + (pm0 + g) * SSTRIDE;
            const float* Pr8 = Pr0 + 8 * SSTRIDE;
#pragma unroll
            for (int kk = 0; kk < 8; kk++) {
                const int k0 = kk * 8;
                float a0 = Pr0[k0 + csel];
                float a1 = Pr8[k0 + csel];
                float a2 = Pr0[k0 + csel + 4];
                float a3 = Pr8[k0 + csel + 4];
                const float* Vk0 = Vb + (k0 + csel) * VSTRIDE + pn0 + g;
                const float* Vk4 = Vk0 + 4 * VSTRIDE;
#pragma unroll
                for (int nt = 0; nt < 8; nt++) {
                    float b0 = Vk0[nt * 8];
                    float b1 = Vk4[nt * 8];
                    mma_tf32(accO[nt][0], accO[nt][1], accO[nt][2], accO[nt][3],
                             a0, a1, a2, a3, b0, b1);
                }
            }
        }
    }

    // ---- normalize + scatter to g_CTXp (permuted A layout, tf32) ----
    {
        float inv0 = 1.f / l_s[pm0 + g];
        float inv1 = 1.f / l_s[pm0 + g + 8];
        int s0    = q0 + pm0 + g;               // s1 = s0+8 (same s_hi)
        int s_hi  = s0 >> 7;
        int s_lo0 = s0 & 127;
        int kin   = ((s_lo0 & 1) << 4) + h;
        int p     = (kin & 3) * 8 + (kin >> 2);
        int idx   = (((p >> 2) ^ (s_hi & 7)) << 2) + (p & 3);
        size_t colb0 = (size_t)((s_lo0 * 16 + h) & ~31) + idx;
        size_t colb1 = colb0 + 128;
        size_t rbase = ((size_t)b * 2048 + s_hi) * HID;
#pragma unroll
        for (int nt = 0; nt < 8; nt++) {
            int d0 = pn0 + nt * 8 + 2 * csel;
            size_t r0 = rbase + (size_t)d0 * 16 * HID;
            size_t r1 = r0 + (size_t)16 * HID;
            g_CTXp[r0 + colb0] = f2tf32f(accO[nt][0] * inv0);
            g_CTXp[r1 + colb0] = f2tf32f(accO[nt][1] * inv0);
            g_CTXp[r0 + colb1] = f2tf32f(accO[nt][2] * inv1);
            g_CTXp[r1 + colb1] = f2tf32f(accO[nt][3] * inv1);
        }
    }
}

// ---------------------------------------------------------------------------
// Launch
// ---------------------------------------------------------------------------
extern "C" void kernel_launch(void* const* d_in, const int* in_sizes, int n_in,
                              void* d_out, int out_size)
{
    (void)in_sizes; (void)n_in; (void)out_size;
    const float* X  = (const float*)d_in[0];
    const float* Wq = (const float*)d_in[1];
    const float* bq = (const float*)d_in[2];
    const float* Wk = (const float*)d_in[3];
    const float* bk = (const float*)d_in[4];
    const float* Wv = (const float*)d_in[5];
    const float* bv = (const float*)d_in[6];
    const float* Wo = (const float*)d_in[7];
    const float* bo = (const float*)d_in[8];
    float* out = (float*)d_out;

    cudaFuncSetAttribute(qkv_gemm_tc, cudaFuncAttributeMaxDynamicSharedMemorySize,
                         GEMM_SMEM_BYTES);
    cudaFuncSetAttribute(out_gemm_tc, cudaFuncAttributeMaxDynamicSharedMemorySize,
                         GEMM_SMEM_BYTES);
    cudaFuncSetAttribute(attn_kernel, cudaFuncAttributeMaxDynamicSharedMemorySize,
                         ATTN_SMEM_BYTES);

    // 0) convert inputs once (X -> permuted tf32, W -> transposed permuted tf32)
    prep_kernel<<<dim3(8192, 1, 5), 256>>>(X, Wq, Wk, Wv, Wo);

    // 1) QKV projections (Q,K permuted; V plain tf32)
    dim3 gq(HID / 128, MROWS / 128, 3);
    qkv_gemm_tc<<<gq, 256, GEMM_SMEM_BYTES>>>(bq, bk, bv);

    // 2) attention (BM=128, 512 threads) -> permuted ctx
    dim3 ga(SEQ / 128, BATCH * NHEADS);
    attn_kernel<<<ga, 512, ATTN_SMEM_BYTES>>>();

    // 3) output projection
    dim3 go(HID / 128, MROWS / 128, 1);
    out_gemm_tc<<<go, 256, GEMM_SMEM_BYTES>>>(bo, out);
}

// round 12
// speedup vs baseline: 1.0394x; 1.0394x over previous
#include <cuda_runtime.h>
#include <math.h>
#include <stdint.h>

// Problem constants
#define HID    2048
#define BATCH  2
#define SEQ    2048
#define NHEADS 16
#define HD     128
#define MROWS  (BATCH * SEQ)   // 4096

// ---------------------------------------------------------------------------
// Scratch (static __device__ arrays — no allocation anywhere)
// ---------------------------------------------------------------------------
__device__ float g_Xp [(size_t)MROWS * HID];          // X, tf32, permuted A layout
__device__ float g_Wp [(size_t)4 * HID * HID];        // W*, tf32, TRANSPOSED [n][k] permuted
__device__ float g_Q  [(size_t)MROWS * HID];          // Q tf32, permuted per-head
__device__ float g_K  [(size_t)MROWS * HID];          // K tf32, permuted per-head
__device__ float g_V  [(size_t)MROWS * HID];          // V tf32, plain
__device__ float g_CTXp[(size_t)MROWS * HID];         // ctx tf32, permuted A layout

// ---------------------------------------------------------------------------
// Helpers
// ---------------------------------------------------------------------------
__device__ __forceinline__ float f2tf32f(float f) {
    uint32_t r;
    asm("cvt.rna.tf32.f32 %0, %1;" : "=r"(r) : "f"(f));
    return __uint_as_float(r);
}
__device__ __forceinline__ uint32_t smem_u32(const void* p) {
    uint32_t a;
    asm("{ .reg .u64 t; cvta.to.shared.u64 t, %1; cvt.u32.u64 %0, t; }"
        : "=r"(a) : "l"(p));
    return a;
}
__device__ __forceinline__ void cp16(uint32_t dst, const void* src) {
    asm volatile("cp.async.cg.shared.global [%0], [%1], 16;"
                 :: "r"(dst), "l"(src));
}
__device__ __forceinline__ void cp_commit() {
    asm volatile("cp.async.commit_group;");
}
template <int N>
__device__ __forceinline__ void cp_wait() {
    asm volatile("cp.async.wait_group %0;" :: "n"(N));
}

__device__ __forceinline__ void mma_tf32(float& d0, float& d1, float& d2, float& d3,
                                         float a0, float a1, float a2, float a3,
                                         float b0, float b1)
{
    asm volatile(
        "mma.sync.aligned.m16n8k8.row.col.f32.tf32.tf32.f32 "
        "{%0,%1,%2,%3}, {%4,%5,%6,%7}, {%8,%9}, {%0,%1,%2,%3};"
        : "+f"(d0), "+f"(d1), "+f"(d2), "+f"(d3)
        : "r"(__float_as_uint(a0)), "r"(__float_as_uint(a1)),
          "r"(__float_as_uint(a2)), "r"(__float_as_uint(a3)),
          "r"(__float_as_uint(b0)), "r"(__float_as_uint(b1)));
}

// ---------------------------------------------------------------------------
// Prep:
//   z=0   : X -> g_Xp  (tf32, permuted A layout)
//   z=1..4: W* -> g_Wp (tf32, TRANSPOSED to [n][k], permuted A layout)
// ---------------------------------------------------------------------------
__global__ __launch_bounds__(256)
void prep_kernel(const float* __restrict__ X,
                 const float* __restrict__ Wq, const float* __restrict__ Wk,
                 const float* __restrict__ Wv, const float* __restrict__ Wo)
{
    const int tid = threadIdx.x;
    const int z = blockIdx.z;
    if (z == 0) {
        const int idx = blockIdx.x * 256 + tid;   // float4 index
        int r   = idx >> 9;
        int rem = idx & 511;
        int c   = rem >> 3;
        int j   = rem & 7;
        float4 v = *(const float4*)(X + (size_t)r * HID + c * 32 + j * 4);
        float* dst = g_Xp + (size_t)r * HID + c * 32;
        const float vv[4] = { v.x, v.y, v.z, v.w };
#pragma unroll
        for (int e = 0; e < 4; e++) {
            int p = e * 8 + j;
            dst[(((p >> 2) ^ (r & 7)) << 2) + (p & 3)] = f2tf32f(vv[e]);
        }
    } else {
        // 64x64 tiled transpose: W[k][n] -> Wt[n][k] (permuted, tf32)
        if (blockIdx.x >= 1024) return;
        __shared__ float ts[64][65];
        const float* W = (z == 1) ? Wq : (z == 2) ? Wk : (z == 3) ? Wv : Wo;
        float* Wt = g_Wp + (size_t)(z - 1) * HID * HID;
        const int k0 = (blockIdx.x & 31) * 64;
        const int n0 = (blockIdx.x >> 5) * 64;

#pragma unroll
        for (int it = 0; it < 4; it++) {
            int idx = tid + it * 256;
            int kk  = idx >> 4;
            int jj  = idx & 15;
            float4 v = *(const float4*)(W + (size_t)(k0 + kk) * HID + n0 + jj * 4);
            ts[jj * 4 + 0][kk] = v.x;
            ts[jj * 4 + 1][kk] = v.y;
            ts[jj * 4 + 2][kk] = v.z;
            ts[jj * 4 + 3][kk] = v.w;
        }
        __syncthreads();

#pragma unroll
        for (int it = 0; it < 4; it++) {
            int idx = tid + it * 256;
            int n   = idx >> 4;
            int rest = idx & 15;
            int c   = rest >> 3;
            int j   = rest & 7;
            float* dst = Wt + (size_t)(n0 + n) * HID + k0 + c * 32;
            int xr = (n0 + n) & 7;
#pragma unroll
            for (int e = 0; e < 4; e++) {
                float v = ts[n][c * 32 + j * 4 + e];
                int p = e * 8 + j;
                dst[(((p >> 2) ^ xr) << 2) + (p & 3)] = f2tf32f(v);
            }
        }
    }
}

// ---------------------------------------------------------------------------
// tf32 mma.sync GEMM v4 (proven R10): C = Aperm @ WtPerm + bias
// Both operands permuted -> all fragment loads LDS.128. 3-stage cp.async,
// CTA 128x128, BK=32, 8 warps (2Mx4N), 2 CTAs/SM.
// ---------------------------------------------------------------------------
#define NSTAGE   3
#define ASTG     4096
#define GEMM_SMEM_FLOATS (NSTAGE * 2 * ASTG)
#define GEMM_SMEM_BYTES  (GEMM_SMEM_FLOATS * 4)

__device__ __forceinline__ void tf32_gemm_body(const float* __restrict__ Ap,
                                               const float* __restrict__ Wt,
                                               const float* __restrict__ bias,
                                               float* __restrict__ C,
                                               int mode)
{
    extern __shared__ float sm[];
    float* smA = sm;
    float* smB = sm + NSTAGE * ASTG;
    const uint32_t smA_u = smem_u32(smA);
    const uint32_t smB_u = smem_u32(smB);

    const int tid   = threadIdx.x;
    const int lane  = tid & 31;
    const int wid   = tid >> 5;
    const int warpM = wid >> 2;
    const int warpN = wid & 3;
    const int csel  = lane & 3;
    const int g     = lane >> 2;

    const int m0 = blockIdx.y * 128;
    const int n0 = blockIdx.x * 128;

    const int lr = tid >> 3;
    const int lj = tid & 7;

    const float* Abase = Ap + (size_t)(m0 + lr) * HID + lj * 4;
    const float* Bbase = Wt + (size_t)(n0 + lr) * HID + lj * 4;
    const uint32_t dA = smA_u + (lr * 32 + lj * 4) * 4;
    const uint32_t dB = smB_u + (lr * 32 + lj * 4) * 4;

    auto load_chunk = [&](int c, int st) {
        const float* As = Abase + c * 32;
        const float* Bs = Bbase + c * 32;
        const uint32_t dAs = dA + st * (ASTG * 4);
        const uint32_t dBs = dB + st * (ASTG * 4);
#pragma unroll
        for (int i = 0; i < 4; i++) {
            cp16(dAs + i * 32 * 32 * 4, As + (size_t)i * 32 * HID);
            cp16(dBs + i * 32 * 32 * 4, Bs + (size_t)i * 32 * HID);
        }
        cp_commit();
    };

    float acc[4][4][4];
#pragma unroll
    for (int mt = 0; mt < 4; mt++)
#pragma unroll
        for (int nt = 0; nt < 4; nt++)
#pragma unroll
            for (int e = 0; e < 4; e++) acc[mt][nt][e] = 0.f;

    auto compute = [&](int st) {
        const float* a = smA + st * ASTG;
        const float* b = smB + st * ASTG;
#pragma unroll
        for (int half = 0; half < 2; half++) {
            const int q = 2 * csel + half;
            float4 A0[4], A8[4];
#pragma unroll
            for (int mt = 0; mt < 4; mt++) {
                int r0 = warpM * 64 + mt * 16 + g;
                int r8 = r0 + 8;
                A0[mt] = *(const float4*)(a + r0 * 32 + ((q ^ (r0 & 7)) * 4));
                A8[mt] = *(const float4*)(a + r8 * 32 + ((q ^ (r8 & 7)) * 4));
            }
#pragma unroll
            for (int nt = 0; nt < 4; nt++) {
                int n = warpN * 32 + nt * 8 + g;
                float4 Bf = *(const float4*)(b + n * 32 + ((q ^ (n & 7)) * 4));
#pragma unroll
                for (int mt = 0; mt < 4; mt++) {
                    mma_tf32(acc[mt][nt][0], acc[mt][nt][1],
                             acc[mt][nt][2], acc[mt][nt][3],
                             A0[mt].x, A8[mt].x, A0[mt].y, A8[mt].y, Bf.x, Bf.y);
                    mma_tf32(acc[mt][nt][0], acc[mt][nt][1],
                             acc[mt][nt][2], acc[mt][nt][3],
                             A0[mt].z, A8[mt].z, A0[mt].w, A8[mt].w, Bf.z, Bf.w);
                }
            }
        }
    };

    load_chunk(0, 0);
    load_chunk(1, 1);

    const int NC = HID / 32;
    for (int c = 0; c < NC; c++) {
        if (c == NC - 1) cp_wait<0>(); else cp_wait<1>();
        __syncthreads();
        compute(c % NSTAGE);
        if (c + 2 < NC) load_chunk(c + 2, (c + 2) % NSTAGE);
    }

    if (mode == 0) {
        const int xg = g & 7;
#pragma unroll
        for (int mt = 0; mt < 4; mt++) {
            int rg0 = m0 + warpM * 64 + mt * 16 + g;
            int rg1 = rg0 + 8;
#pragma unroll
            for (int nt = 0; nt < 4; nt++) {
                int kin0 = nt * 8 + 2 * csel;
                int colb = n0 + warpN * 32;
                int p0   = (kin0 & 3) * 8 + (kin0 >> 2);
                int x    = p0 >> 2, lo = p0 & 3;
                int idx0 = ((x ^ xg) << 2) + lo;
                int idx1 = (((x + 2) ^ xg) << 2) + lo;
                float b0 = __ldg(bias + colb + kin0);
                float b1 = __ldg(bias + colb + kin0 + 1);
                C[(size_t)rg0 * HID + colb + idx0] = f2tf32f(acc[mt][nt][0] + b0);
                C[(size_t)rg0 * HID + colb + idx1] = f2tf32f(acc[mt][nt][1] + b1);
                C[(size_t)rg1 * HID + colb + idx0] = f2tf32f(acc[mt][nt][2] + b0);
                C[(size_t)rg1 * HID + colb + idx1] = f2tf32f(acc[mt][nt][3] + b1);
            }
        }
    } else {
#pragma unroll
        for (int mt = 0; mt < 4; mt++) {
            int row = m0 + warpM * 64 + mt * 16 + g;
#pragma unroll
            for (int nt = 0; nt < 4; nt++) {
                int col = n0 + warpN * 32 + nt * 8 + 2 * csel;
                float b0 = __ldg(bias + col);
                float b1 = __ldg(bias + col + 1);
                float v0 = acc[mt][nt][0] + b0, v1 = acc[mt][nt][1] + b1;
                float v2 = acc[mt][nt][2] + b0, v3 = acc[mt][nt][3] + b1;
                if (mode == 1) {
                    v0 = f2tf32f(v0); v1 = f2tf32f(v1);
                    v2 = f2tf32f(v2); v3 = f2tf32f(v3);
                }
                *(float2*)(C + (size_t)row * HID + col)       = make_float2(v0, v1);
                *(float2*)(C + (size_t)(row + 8) * HID + col) = make_float2(v2, v3);
            }
        }
    }
}

__global__ __launch_bounds__(256, 2)
void qkv_gemm_tc(const float* __restrict__ bq,
                 const float* __restrict__ bk,
                 const float* __restrict__ bv)
{
    const float* Wz; const float* b; float* Cp; int mode;
    if (blockIdx.z == 0)      { Wz = g_Wp;                     b = bq; Cp = g_Q; mode = 0; }
    else if (blockIdx.z == 1) { Wz = g_Wp + (size_t)HID*HID;   b = bk; Cp = g_K; mode = 0; }
    else                      { Wz = g_Wp + (size_t)2*HID*HID; b = bv; Cp = g_V; mode = 1; }
    tf32_gemm_body(g_Xp, Wz, b, Cp, mode);
}

__global__ __launch_bounds__(256, 2)
void out_gemm_tc(const float* __restrict__ bo, float* __restrict__ out)
{
    tf32_gemm_body(g_CTXp, g_Wp + (size_t)3 * HID * HID, bo, out, 2);
}

// ---------------------------------------------------------------------------
// Attention v5 (proven R9 config): 256 threads, BM=128, 8 warps, each owning
// a 16-row slab (full 64 key cols for S, full 128 d cols for O).
// K reloaded during softmax+PV (dead after S), V double-buffered.
// Output -> g_CTXp (permuted A layout, tf32).
// ---------------------------------------------------------------------------
#define SSTRIDE 68
#define VSTRIDE 136
#define VBUF    (64 * VSTRIDE)
#define ATTN_SMEM_FLOATS (16384 + 8192 + 2 * VBUF + 128 * SSTRIDE + 384)
#define ATTN_SMEM_BYTES  (ATTN_SMEM_FLOATS * 4)

__global__ __launch_bounds__(256)
void attn_kernel()
{
    extern __shared__ float smf[];
    float* Qs  = smf;                    // 4 chunks x 128 x 32 (permuted tf32)
    float* Ks  = Qs + 16384;             // 4 chunks x 64 x 32
    float* Vs  = Ks + 8192;              // 2 x (64 x VSTRIDE)
    float* Ss  = Vs + 2 * VBUF;          // 128 x SSTRIDE
    float* m_s = Ss + 128 * SSTRIDE;     // 128
    float* l_s = m_s + 128;
    float* a_s = l_s + 128;
    const uint32_t Qs_u = smem_u32(Qs);
    const uint32_t Ks_u = smem_u32(Ks);
    const uint32_t Vs_u = smem_u32(Vs);

    const int tid  = threadIdx.x;
    const int lane = tid & 31;
    const int wid  = tid >> 5;           // warp owns rows [wid*16, wid*16+16)
    const int csel = lane & 3;
    const int g    = lane >> 2;

    const int bh  = blockIdx.y;
    const int b   = bh >> 4;
    const int h   = bh & 15;
    const int q0  = blockIdx.x * 128;
    const size_t rowbase = (size_t)b * SEQ;
    const float scale = 0.08838834764831845f;   // 1/sqrt(128)

    const int pm0 = wid * 16;

    // ---- Q tile: 128 rows x 128 d -> permuted layout ----
    {
        const float* Qg = g_Q + (rowbase + q0) * HID + h * HD;
#pragma unroll
        for (int it = 0; it < 16; it++) {
            int idx = tid + it * 256;
            int r   = idx >> 5;
            int rem = idx & 31;
            cp16(Qs_u + (((rem >> 3) * 4096 + r * 32 + (rem & 7) * 4) * 4),
                 Qg + (size_t)r * HID + rem * 4);
        }
    }
    // ---- preload K/V tile 0 ----
    {
        const float* Kg = g_K + rowbase * HID + h * HD;
        const float* Vg = g_V + rowbase * HID + h * HD;
#pragma unroll
        for (int it = 0; it < 8; it++) {
            int idx = tid + it * 256;
            int r   = idx >> 5;
            int rem = idx & 31;
            cp16(Ks_u + (((rem >> 3) * 2048 + r * 32 + (rem & 7) * 4) * 4),
                 Kg + (size_t)r * HID + rem * 4);
            cp16(Vs_u + ((r * VSTRIDE + rem * 4) * 4),
                 Vg + (size_t)r * HID + rem * 4);
        }
        cp_commit();
    }
    if (tid < 128) { m_s[tid] = -INFINITY; l_s[tid] = 0.f; }

    float accO[16][4];
#pragma unroll
    for (int nt = 0; nt < 16; nt++)
#pragma unroll
        for (int e = 0; e < 4; e++) accO[nt][e] = 0.f;

    const int NT = SEQ / 64;   // 32
    for (int jt = 0; jt < NT; jt++) {
        cp_wait<0>();
        __syncthreads();       // loads ready; prior-iter readers of Ss/Vs done

        // ---- S = (Q K^T): warp tile 16 x 64 ----
        {
            float accS[8][4];
#pragma unroll
            for (int nt = 0; nt < 8; nt++)
#pragma unroll
                for (int e = 0; e < 4; e++) accS[nt][e] = 0.f;

#pragma unroll
            for (int ch = 0; ch < 4; ch++) {
                const float* qa = Qs + ch * 4096;
                const float* kb = Ks + ch * 2048;
#pragma unroll
                for (int half = 0; half < 2; half++) {
                    const int q = 2 * csel + half;
                    int r0 = pm0 + g;
                    int r8 = r0 + 8;
                    float4 A0 = *(const float4*)(qa + r0 * 32 + ((q ^ (r0 & 7)) * 4));
                    float4 A8 = *(const float4*)(qa + r8 * 32 + ((q ^ (r8 & 7)) * 4));
#pragma unroll
                    for (int nt = 0; nt < 8; nt++) {
                        int n = nt * 8 + g;
                        float4 Bf = *(const float4*)(kb + n * 32 + ((q ^ (n & 7)) * 4));
                        mma_tf32(accS[nt][0], accS[nt][1], accS[nt][2], accS[nt][3],
                                 A0.x, A8.x, A0.y, A8.y, Bf.x, Bf.y);
                        mma_tf32(accS[nt][0], accS[nt][1], accS[nt][2], accS[nt][3],
                                 A0.z, A8.z, A0.w, A8.w, Bf.z, Bf.w);
                    }
                }
            }
            int row0 = pm0 + g;
#pragma unroll
            for (int nt = 0; nt < 8; nt++) {
                int col = nt * 8 + 2 * csel;
                *(float2*)(Ss + row0 * SSTRIDE + col) =
                    make_float2(accS[nt][0] * scale, accS[nt][1] * scale);
                *(float2*)(Ss + (row0 + 8) * SSTRIDE + col) =
                    make_float2(accS[nt][2] * scale, accS[nt][3] * scale);
            }
        }
        __syncthreads();       // Ks fully consumed; Ss written

        // ---- prefetch K/V for jt+1 (overlaps softmax + PV) ----
        if (jt + 1 < NT) {
            const float* Kg = g_K + (rowbase + (jt + 1) * 64) * HID + h * HD;
            const float* Vg = g_V + (rowbase + (jt + 1) * 64) * HID + h * HD;
            const uint32_t vb = ((jt + 1) & 1) * (VBUF * 4);
#pragma unroll
            for (int it = 0; it < 8; it++) {
                int idx = tid + it * 256;
                int r   = idx >> 5;
                int rem = idx & 31;
                cp16(Ks_u + (((rem >> 3) * 2048 + r * 32 + (rem & 7) * 4) * 4),
                     Kg + (size_t)r * HID + rem * 4);
                cp16(Vs_u + vb + ((r * VSTRIDE + rem * 4) * 4),
                     Vg + (size_t)r * HID + rem * 4);
            }
            cp_commit();
        }

        // ---- online softmax: 2 threads per row (32 cols each) ----
        {
            const int r  = tid >> 1;
            const int qd = tid & 1;
            float* srow = Ss + r * SSTRIDE + qd * 32;
            float mold = m_s[r];
            float mx = mold;
#pragma unroll
            for (int c = 0; c < 32; c++) mx = fmaxf(mx, srow[c]);
            mx = fmaxf(mx, __shfl_xor_sync(0xFFFFFFFFu, mx, 1));
            float ls = 0.f;
#pragma unroll
            for (int c = 0; c < 32; c++) {
                float p = __expf(srow[c] - mx);
                srow[c] = f2tf32f(p);
                ls += p;
            }
            ls += __shfl_xor_sync(0xFFFFFFFFu, ls, 1);
            if (qd == 0) {
                float alpha = __expf(mold - mx);
                m_s[r] = mx;
                l_s[r] = l_s[r] * alpha + ls;
                a_s[r] = alpha;
            }
        }
        __syncthreads();

        // ---- O += P @ V : warp tile 16 x 128 ----
        {
            const float* Vb = Vs + (jt & 1) * VBUF;
            float al0 = a_s[pm0 + g];
            float al1 = a_s[pm0 + g + 8];
#pragma unroll
            for (int nt = 0; nt < 16; nt++) {
                accO[nt][0] *= al0;  accO[nt][1] *= al0;
                accO[nt][2] *= al1;  accO[nt][3] *= al1;
            }
            const float* Pr0 = Ss + (pm0 + g) * SSTRIDE;
            const float* Pr8 = Pr0 + 8 * SSTRIDE;
#pragma unroll
            for (int kk = 0; kk < 8; kk++) {
                const int k0 = kk * 8;
                float a0 = Pr0[k0 + csel];
                float a1 = Pr8[k0 + csel];
                float a2 = Pr0[k0 + csel + 4];
                float a3 = Pr8[k0 + csel + 4];
                const float* Vk0 = Vb + (k0 + csel) * VSTRIDE + g;
                const float* Vk4 = Vk0 + 4 * VSTRIDE;
#pragma unroll
                for (int nt = 0; nt < 16; nt++) {
                    float b0 = Vk0[nt * 8];
                    float b1 = Vk4[nt * 8];
                    mma_tf32(accO[nt][0], accO[nt][1], accO[nt][2], accO[nt][3],
                             a0, a1, a2, a3, b0, b1);
                }
            }
        }
    }

    // ---- normalize + scatter to g_CTXp (permuted A layout, tf32) ----
    {
        float inv0 = 1.f / l_s[pm0 + g];
        float inv1 = 1.f / l_s[pm0 + g + 8];
        int s0    = q0 + pm0 + g;               // s1 = s0+8 (same s_hi)
        int s_hi  = s0 >> 7;
        int s_lo0 = s0 & 127;
        int kin   = ((s_lo0 & 1) << 4) + h;
        int p     = (kin & 3) * 8 + (kin >> 2);
        int idx   = (((p >> 2) ^ (s_hi & 7)) << 2) + (p & 3);
        size_t colb0 = (size_t)((s_lo0 * 16 + h) & ~31) + idx;
        size_t colb1 = colb0 + 128;
        size_t rbase = ((size_t)b * 2048 + s_hi) * HID;
#pragma unroll
        for (int nt = 0; nt < 16; nt++) {
            int d0 = nt * 8 + 2 * csel;
            size_t r0 = rbase + (size_t)d0 * 16 * HID;
            size_t r1 = r0 + (size_t)16 * HID;
            g_CTXp[r0 + colb0] = f2tf32f(accO[nt][0] * inv0);
            g_CTXp[r1 + colb0] = f2tf32f(accO[nt][1] * inv0);
            g_CTXp[r0 + colb1] = f2tf32f(accO[nt][2] * inv1);
            g_CTXp[r1 + colb1] = f2tf32f(accO[nt][3] * inv1);
        }
    }
}

// ---------------------------------------------------------------------------
// Launch
// ---------------------------------------------------------------------------
extern "C" void kernel_launch(void* const* d_in, const int* in_sizes, int n_in,
                              void* d_out, int out_size)
{
    (void)in_sizes; (void)n_in; (void)out_size;
    const float* X  = (const float*)d_in[0];
    const float* Wq = (const float*)d_in[1];
    const float* bq = (const float*)d_in[2];
    const float* Wk = (const float*)d_in[3];
    const float* bk = (const float*)d_in[4];
    const float* Wv = (const float*)d_in[5];
    const float* bv = (const float*)d_in[6];
    const float* Wo = (const float*)d_in[7];
    const float* bo = (const float*)d_in[8];
    float* out = (float*)d_out;

    cudaFuncSetAttribute(qkv_gemm_tc, cudaFuncAttributeMaxDynamicSharedMemorySize,
                         GEMM_SMEM_BYTES);
    cudaFuncSetAttribute(out_gemm_tc, cudaFuncAttributeMaxDynamicSharedMemorySize,
                         GEMM_SMEM_BYTES);
    cudaFuncSetAttribute(attn_kernel, cudaFuncAttributeMaxDynamicSharedMemorySize,
                         ATTN_SMEM_BYTES);

    // 0) convert inputs once (X -> permuted tf32, W -> transposed permuted tf32)
    prep_kernel<<<dim3(8192, 1, 5), 256>>>(X, Wq, Wk, Wv, Wo);

    // 1) QKV projections (Q,K permuted; V plain tf32)
    dim3 gq(HID / 128, MROWS / 128, 3);
    qkv_gemm_tc<<<gq, 256, GEMM_SMEM_BYTES>>>(bq, bk, bv);

    // 2) attention (BM=128, 256 threads) -> permuted ctx
    dim3 ga(SEQ / 128, BATCH * NHEADS);
    attn_kernel<<<ga, 256, ATTN_SMEM_BYTES>>>();

    // 3) output projection
    dim3 go(HID / 128, MROWS / 128, 1);
    out_gemm_tc<<<go, 256, GEMM_SMEM_BYTES>>>(bo, out);
}